// round 15
// baseline (speedup 1.0000x reference)
#include <cuda_runtime.h>
#include <cuda_bf16.h>
#include <cuda_fp16.h>
#include <math.h>
#include <stdint.h>

#define NN 100000
#define EE 1600000
#define HH 128
#define CC 40

// Scratch (device globals — allocation-free per harness rules)
__device__ __half g_xr16a[(size_t)NN * HH]; // layer1 rel features (fp16 gather source)
__device__ __half g_xr16b[(size_t)NN * HH]; // layer2 rel features (fp16 gather source)
__device__ float  g_z1[(size_t)NN * HH];    // layer1 root part: x@W_root1 + b1
__device__ float  g_z2[(size_t)NN * HH];    // layer2 root part
__device__ __half g_x1h[(size_t)NN * HH];   // relu(z1) fp16, for final concat
// Pre-split weights [n][k] K-major: [rel1_h, rel1_l, root1_h, root1_l,
//                                    rel2_h, rel2_l, root2_h, root2_l]
__device__ __align__(16) __nv_bfloat16 g_wsp[8 * 16384];
// W_lin pre-split, padded to [64][256] bf16 K-major: [hi, lo]
__device__ __align__(16) __nv_bfloat16 g_wlin[2 * 16384];
// CSR scratch
__device__ int g_rowptr[NN + 1];
__device__ int g_cursor[NN];
__device__ int g_perm[EE];
__device__ int g_bsum[128];

// ---------------------------------------------------------------------------
// helpers
// ---------------------------------------------------------------------------
__device__ __forceinline__ uint32_t smem_u32(const void* p) {
    uint32_t a;
    asm("{ .reg .u64 t; cvta.to.shared.u64 t, %1; cvt.u32.u64 %0, t; }"
        : "=r"(a) : "l"(p));
    return a;
}

#define LDSM4(r, addr) \
    asm volatile("ldmatrix.sync.aligned.m8n8.x4.shared.b16 {%0,%1,%2,%3}, [%4];" \
        : "=r"((r)[0]), "=r"((r)[1]), "=r"((r)[2]), "=r"((r)[3]) : "r"(addr))

#define HMMA(c, a, b) \
    asm volatile("mma.sync.aligned.m16n8k16.row.col.f32.bf16.bf16.f32 " \
        "{%0,%1,%2,%3}, {%4,%5,%6,%7}, {%8,%9}, {%0,%1,%2,%3};" \
        : "+f"((c)[0]), "+f"((c)[1]), "+f"((c)[2]), "+f"((c)[3]) \
        : "r"((a)[0]), "r"((a)[1]), "r"((a)[2]), "r"((a)[3]), \
          "r"((b)[0]), "r"((b)[1]))

#define CP_ASYNC16(dst, src) \
    asm volatile("cp.async.cg.shared.global [%0], [%1], 16;" \
                 :: "r"(dst), "l"(src) : "memory")

__device__ __forceinline__ void acc4(float4& a, uint2 r) {
    float2 f0 = __half22float2(*reinterpret_cast<const __half2*>(&r.x));
    float2 f1 = __half22float2(*reinterpret_cast<const __half2*>(&r.y));
    a.x += f0.x; a.y += f0.y; a.z += f1.x; a.w += f1.y;
}

// ---------------------------------------------------------------------------
// Weight prep: split each 128x128 W ([k][n]) into bf16 hi/lo, transposed to
// [n][k] K-major linear. Tiny one-shot kernel.
// ---------------------------------------------------------------------------
__global__ void prep_w(const float* __restrict__ Wr1, const float* __restrict__ Wt1,
                       const float* __restrict__ Wr2, const float* __restrict__ Wt2)
{
    int idx = blockIdx.x * 256 + threadIdx.x;   // 0..16383
    const float* src = (blockIdx.y == 0) ? Wr1 : (blockIdx.y == 1) ? Wt1
                     : (blockIdx.y == 2) ? Wr2 : Wt2;
    float w = src[idx];                          // W[k][n]
    int k = idx >> 7, n = idx & 127;
    __nv_bfloat16 h = __float2bfloat16(w);
    __nv_bfloat16 l = __float2bfloat16(w - __bfloat162float(h));
    int tb = blockIdx.y * 2;
    g_wsp[(size_t)tb * 16384 + n * 128 + k] = h;
    g_wsp[(size_t)(tb + 1) * 16384 + n * 128 + k] = l;
}

// W_lin [256][40] -> padded [64][256] bf16 hi/lo, [c][k] K-major
__global__ void prep_wlin(const float* __restrict__ Wlin)
{
    int idx = blockIdx.x * 256 + threadIdx.x;   // 0..16383
    int c = idx >> 8, k = idx & 255;
    float w = (c < CC) ? Wlin[k * CC + c] : 0.f;
    __nv_bfloat16 h = __float2bfloat16(w);
    __nv_bfloat16 l = __float2bfloat16(w - __bfloat162float(h));
    g_wlin[idx] = h;
    g_wlin[16384 + idx] = l;
}

// ---------------------------------------------------------------------------
// CSR build kernels
// ---------------------------------------------------------------------------
__global__ void k_zero() {
    int i = blockIdx.x * 256 + threadIdx.x;
    if (i < NN) g_cursor[i] = 0;
}
__global__ void k_count(const int* __restrict__ ei) {
    int e = blockIdx.x * 256 + threadIdx.x;
    if (e < EE) atomicAdd(&g_cursor[__ldg(ei + EE + e)], 1);
}
__global__ void k_scan(void) {
    __shared__ int wsum[8];
    __shared__ int wexc[8];
    int t = threadIdx.x, b = blockIdx.x;
    int base = b * 1024 + t * 4;
    int x0 = (base + 0 < NN) ? g_cursor[base + 0] : 0;
    int x1 = (base + 1 < NN) ? g_cursor[base + 1] : 0;
    int x2 = (base + 2 < NN) ? g_cursor[base + 2] : 0;
    int x3 = (base + 3 < NN) ? g_cursor[base + 3] : 0;
    int s1 = x0, s2 = x0 + x1, s3 = x0 + x1 + x2, T = s3 + x3;
    int lane = t & 31, w = t >> 5;
    int inc = T;
    #pragma unroll
    for (int d = 1; d < 32; d <<= 1) {
        int v = __shfl_up_sync(0xffffffffu, inc, d);
        if (lane >= d) inc += v;
    }
    int wex = inc - T;
    if (lane == 31) wsum[w] = inc;
    __syncthreads();
    if (t == 0) {
        int r = 0;
        #pragma unroll
        for (int i = 0; i < 8; i++) { int v = wsum[i]; wexc[i] = r; r += v; }
        g_bsum[b] = r;
    }
    __syncthreads();
    int ex = wexc[w] + wex;
    if (base + 0 < NN) g_rowptr[base + 0] = ex;
    if (base + 1 < NN) g_rowptr[base + 1] = ex + s1;
    if (base + 2 < NN) g_rowptr[base + 2] = ex + s2;
    if (base + 3 < NN) g_rowptr[base + 3] = ex + s3;
}
__global__ void k_scan2(void) {       // exclusive scan of 98 block sums
    __shared__ int s[128];
    int t = threadIdx.x;
    s[t] = (t < 98) ? g_bsum[t] : 0;
    __syncthreads();
    if (t == 0) {
        int r = 0;
        for (int i = 0; i < 98; i++) { int v = s[i]; s[i] = r; r += v; }
    }
    __syncthreads();
    if (t < 98) g_bsum[t] = s[t];
}
__global__ void k_apply(void) {
    int i = blockIdx.x * 256 + threadIdx.x;
    if (i < NN) {
        int v = g_rowptr[i] + g_bsum[i >> 10];
        g_rowptr[i] = v;
        g_cursor[i] = v;
    }
    if (i == 0) g_rowptr[NN] = EE;
}
__global__ void k_place(const int* __restrict__ ei) {
    int e = blockIdx.x * 256 + threadIdx.x;
    if (e < EE) {
        int d = __ldg(ei + EE + e);
        int p = atomicAdd(&g_cursor[d], 1);
        g_perm[p] = __ldg(ei + e);
    }
}

// ---------------------------------------------------------------------------
// Layer GEMM: one CTA = 128 rows, computes BOTH A@W_rel -> xr16 out (fp16) and
// A@W_root + b -> z (two sequential N-phases). bf16 hi/lo split, fp32 accum.
// LAYER==1: A = x (fp32 global); rel out -> g_xr16a.
// LAYER==2: A = relu(g_z1 + agg gathered from g_xr16a) (gather fused in
//           stage A); writes x1 = relu(...) to g_x1h; rel out -> g_xr16b.
//           (Separate buffers: other CTAs still gather layer-1 values.)
// 512 threads (16 warps: 4M x 4N). Weights staged via cp.async.
// ---------------------------------------------------------------------------
#define OFF_AH 0
#define OFF_AL 32768
#define OFF_W  65536          // 4 tiles: rel_h, rel_l, root_h, root_l (32KB each)
#define LSMEM  196608

template <int LAYER>
__global__ __launch_bounds__(512, 1) void layer_mma(
    const float* __restrict__ Ain, const float* __restrict__ bias)
{
    extern __shared__ char smem[];
    const uint32_t sb = smem_u32(smem);
    const int tid = threadIdx.x, wid = tid >> 5, lane = tid & 31;
    const int m0 = blockIdx.x * 128;

    float* outz = (LAYER == 1) ? g_z1 : g_z2;
    __half* outxr = (LAYER == 1) ? g_xr16a : g_xr16b;
    const __nv_bfloat16* wsrc = g_wsp + (size_t)(LAYER - 1) * 4 * 16384;

    // ---- weights: 4 tiles (128KB) via cp.async into swizzled smem ----
    {
        const float4* ws = (const float4*)wsrc;   // 8192 float4
        #pragma unroll
        for (int i = 0; i < 16; i++) {
            int s = tid + i * 512;                // 0..8191
            int t4 = s >> 11;
            int r = s & 2047;
            int n = r >> 4, c = r & 15;
            uint32_t dst = sb + OFF_W + t4 * 32768
                         + (uint32_t)(n * 256 + ((c * 16) ^ ((n & 7) << 4)));
            CP_ASYNC16(dst, ws + s);
        }
        asm volatile("cp.async.commit_group;" ::: "memory");
    }

    // ---- Stage A: build A tile (hi/lo split) ----
    if (LAYER == 1) {
        #pragma unroll
        for (int i = 0; i < 8; i++) {
            int f = tid + i * 512;                // 0..4095 float4 slots
            int row = f >> 5;
            int k4 = (f & 31) << 2;
            int gm = m0 + row;
            float4 v = make_float4(0.f, 0.f, 0.f, 0.f);
            if (gm < NN) v = *(const float4*)(Ain + (size_t)gm * HH + k4);
            __nv_bfloat16 h0 = __float2bfloat16(v.x), h1 = __float2bfloat16(v.y);
            __nv_bfloat16 h2 = __float2bfloat16(v.z), h3 = __float2bfloat16(v.w);
            __nv_bfloat16 l0 = __float2bfloat16(v.x - __bfloat162float(h0));
            __nv_bfloat16 l1 = __float2bfloat16(v.y - __bfloat162float(h1));
            __nv_bfloat16 l2 = __float2bfloat16(v.z - __bfloat162float(h2));
            __nv_bfloat16 l3 = __float2bfloat16(v.w - __bfloat162float(h3));
            uint32_t off = (uint32_t)(row * 256 + ((k4 * 2) ^ ((row & 7) << 4)));
            __nv_bfloat162* ph = (__nv_bfloat162*)(smem + OFF_AH + off);
            __nv_bfloat162* pl = (__nv_bfloat162*)(smem + OFF_AL + off);
            ph[0] = __halves2bfloat162(h0, h1); ph[1] = __halves2bfloat162(h2, h3);
            pl[0] = __halves2bfloat162(l0, l1); pl[1] = __halves2bfloat162(l2, l3);
        }
    } else {
        // fused gather from g_xr16a (layer-1 features): each warp builds 8 rows
        const size_t fo = (size_t)lane * 4;
        #pragma unroll 1
        for (int i = 0; i < 8; i++) {
            int lrow = wid * 8 + i;
            int node = m0 + lrow;
            float4 v = make_float4(0.f, 0.f, 0.f, 0.f);
            if (node < NN) {
                int s = g_rowptr[node], e = g_rowptr[node + 1];
                float4 a0 = v, a1 = v, a2 = v, a3 = v;
                int j = s;
                for (; j + 3 < e; j += 4) {
                    int p0 = __ldg(g_perm + j),     p1 = __ldg(g_perm + j + 1);
                    int p2 = __ldg(g_perm + j + 2), p3 = __ldg(g_perm + j + 3);
                    acc4(a0, *(const uint2*)(g_xr16a + (size_t)p0 * HH + fo));
                    acc4(a1, *(const uint2*)(g_xr16a + (size_t)p1 * HH + fo));
                    acc4(a2, *(const uint2*)(g_xr16a + (size_t)p2 * HH + fo));
                    acc4(a3, *(const uint2*)(g_xr16a + (size_t)p3 * HH + fo));
                }
                for (; j < e; j++)
                    acc4(a0, *(const uint2*)(g_xr16a + (size_t)__ldg(g_perm + j) * HH + fo));
                float4 zr = *(const float4*)(g_z1 + (size_t)node * HH + fo);
                v.x = fmaxf(zr.x + (a0.x + a1.x) + (a2.x + a3.x), 0.f);
                v.y = fmaxf(zr.y + (a0.y + a1.y) + (a2.y + a3.y), 0.f);
                v.z = fmaxf(zr.z + (a0.z + a1.z) + (a2.z + a3.z), 0.f);
                v.w = fmaxf(zr.w + (a0.w + a1.w) + (a2.w + a3.w), 0.f);
                __half2 p0 = __floats2half2_rn(v.x, v.y);
                __half2 p1 = __floats2half2_rn(v.z, v.w);
                uint2 o = make_uint2(*(uint32_t*)&p0, *(uint32_t*)&p1);
                *(uint2*)(g_x1h + (size_t)node * HH + fo) = o;
            }
            int k4 = lane * 4;
            __nv_bfloat16 h0 = __float2bfloat16(v.x), h1 = __float2bfloat16(v.y);
            __nv_bfloat16 h2 = __float2bfloat16(v.z), h3 = __float2bfloat16(v.w);
            __nv_bfloat16 l0 = __float2bfloat16(v.x - __bfloat162float(h0));
            __nv_bfloat16 l1 = __float2bfloat16(v.y - __bfloat162float(h1));
            __nv_bfloat16 l2 = __float2bfloat16(v.z - __bfloat162float(h2));
            __nv_bfloat16 l3 = __float2bfloat16(v.w - __bfloat162float(h3));
            uint32_t off = (uint32_t)(lrow * 256 + ((k4 * 2) ^ ((lrow & 7) << 4)));
            __nv_bfloat162* ph = (__nv_bfloat162*)(smem + OFF_AH + off);
            __nv_bfloat162* pl = (__nv_bfloat162*)(smem + OFF_AL + off);
            ph[0] = __halves2bfloat162(h0, h1); ph[1] = __halves2bfloat162(h2, h3);
            pl[0] = __halves2bfloat162(l0, l1); pl[1] = __halves2bfloat162(l2, l3);
        }
    }
    asm volatile("cp.async.wait_group 0;" ::: "memory");
    __syncthreads();

    // ---- warp tiling: 4(M) x 4(N); warp tile M32 x N32 ----
    const int mbase = (wid >> 2) * 32;
    const int nbase = (wid & 3) * 32;
    const int qr = lane & 7, qs = lane >> 3;

    const int arow = mbase + (qs & 1) * 8 + qr;
    const uint32_t aph = (uint32_t)((arow & 7) << 4);
    const uint32_t akc = (uint32_t)((qs >> 1) * 16);
    const uint32_t aH = sb + OFF_AH + arow * 256;
    const uint32_t aL = sb + OFF_AL + arow * 256;
    const int brow = nbase + (qs >> 1) * 8 + qr;
    const uint32_t bph = (uint32_t)((brow & 7) << 4);
    const uint32_t bkc = (uint32_t)((qs & 1) * 16);
    const uint32_t brofs = (uint32_t)(brow * 256);

    #pragma unroll
    for (int which = 0; which < 2; which++) {
        const uint32_t wHb = sb + OFF_W + which * 65536 + brofs;
        const uint32_t wLb = wHb + 32768;

        float acc[2][4][4];
        #pragma unroll
        for (int mt = 0; mt < 2; mt++)
            #pragma unroll
            for (int nt = 0; nt < 4; nt++)
                #pragma unroll
                for (int q = 0; q < 4; q++) acc[mt][nt][q] = 0.f;

        #pragma unroll
        for (int ks = 0; ks < 8; ks++) {
            const uint32_t ao = (akc + ks * 32) ^ aph;
            const uint32_t bo = (bkc + ks * 32) ^ bph;
            uint32_t ah[2][4], al[2][4], bh[2][4], bl[2][4];
            LDSM4(ah[0], aH + ao); LDSM4(ah[1], aH + 4096 + ao);
            LDSM4(al[0], aL + ao); LDSM4(al[1], aL + 4096 + ao);
            LDSM4(bh[0], wHb + bo); LDSM4(bh[1], wHb + 4096 + bo);
            LDSM4(bl[0], wLb + bo); LDSM4(bl[1], wLb + 4096 + bo);
            #pragma unroll
            for (int mt = 0; mt < 2; mt++)
                #pragma unroll
                for (int nt = 0; nt < 4; nt++) {
                    uint32_t* Bh = &bh[nt >> 1][2 * (nt & 1)];
                    uint32_t* Bl = &bl[nt >> 1][2 * (nt & 1)];
                    HMMA(acc[mt][nt], ah[mt], Bh);
                    HMMA(acc[mt][nt], ah[mt], Bl);
                    HMMA(acc[mt][nt], al[mt], Bh);
                }
        }

        #pragma unroll
        for (int mt = 0; mt < 2; mt++) {
            int mrow = m0 + mbase + mt * 16 + (lane >> 2);
            #pragma unroll
            for (int nt = 0; nt < 4; nt++) {
                int col = nbase + nt * 8 + 2 * (lane & 3);
                if (which) {
                    float bx = __ldg(bias + col), by = __ldg(bias + col + 1);
                    if (mrow < NN)
                        *(float2*)(outz + (size_t)mrow * HH + col) =
                            make_float2(acc[mt][nt][0] + bx, acc[mt][nt][1] + by);
                    if (mrow + 8 < NN)
                        *(float2*)(outz + (size_t)(mrow + 8) * HH + col) =
                            make_float2(acc[mt][nt][2] + bx, acc[mt][nt][3] + by);
                } else {
                    if (mrow < NN) {
                        __half2 hv = __floats2half2_rn(acc[mt][nt][0], acc[mt][nt][1]);
                        *(uint32_t*)(outxr + (size_t)mrow * HH + col) = *(uint32_t*)&hv;
                    }
                    if (mrow + 8 < NN) {
                        __half2 hv = __floats2half2_rn(acc[mt][nt][2], acc[mt][nt][3]);
                        *(uint32_t*)(outxr + (size_t)(mrow + 8) * HH + col) = *(uint32_t*)&hv;
                    }
                }
            }
        }
    }
}

// ---------------------------------------------------------------------------
// Fused gather2 + final (HMMA): per 128-node CTA,
//   stage A: warp-per-node gather agg from g_xr16b (fp16), + g_z2 root, relu;
//            x1 from g_x1h (fp16, already relu'd); H = [x1|z2] bf16 hi/lo.
//   stage B: logits = H @ W_lin^T via m16n8k16 (3-product split), bias +
//            log_softmax from smem logits. 512 threads.
// ---------------------------------------------------------------------------
#define F_AH 0                 // 128 x 512B (bf16 hi)
#define F_AL 65536             // 128 x 512B (bf16 lo)
#define F_WH 131072            // 64 x 512B
#define F_WL 163840            // 64 x 512B
#define F_BIAS 196608          // 40 floats
#define FSMEM  196864

__global__ __launch_bounds__(512, 1) void final_fused(
    const float* __restrict__ blin, float* __restrict__ out)
{
    extern __shared__ char smem[];
    const uint32_t sb = smem_u32(smem);
    const int tid = threadIdx.x, wid = tid >> 5, lane = tid & 31;
    const int n0 = blockIdx.x * 128;

    // ---- W_lin hi/lo tiles (64KB) via cp.async ----
    {
        const float4* ws = (const float4*)g_wlin;  // 4096 uint4
        #pragma unroll
        for (int i = 0; i < 8; i++) {
            int s = tid + i * 512;                 // 0..4095
            int t4 = s >> 11;                      // 0 hi, 1 lo
            int r = s & 2047;
            int n = r >> 5, c = r & 31;
            uint32_t dst = sb + F_WH + t4 * 32768
                         + (uint32_t)(n * 512 + ((c * 16) ^ ((n & 7) << 4)));
            CP_ASYNC16(dst, ws + s);
        }
        asm volatile("cp.async.commit_group;" ::: "memory");
    }
    if (tid < CC) ((float*)(smem + F_BIAS))[tid] = blin[tid];

    // ---- Stage A: gather + convert; each warp handles 8 nodes ----
    const size_t fo = (size_t)lane * 4;
    #pragma unroll 1
    for (int i = 0; i < 8; i++) {
        int node = n0 + wid * 8 + i;
        int lrow = wid * 8 + i;
        if (node < NN) {
            int s = g_rowptr[node], e = g_rowptr[node + 1];
            float4 a0 = make_float4(0.f, 0.f, 0.f, 0.f), a1 = a0, a2 = a0, a3 = a0;
            int j = s;
            for (; j + 3 < e; j += 4) {
                int p0 = __ldg(g_perm + j),     p1 = __ldg(g_perm + j + 1);
                int p2 = __ldg(g_perm + j + 2), p3 = __ldg(g_perm + j + 3);
                acc4(a0, *(const uint2*)(g_xr16b + (size_t)p0 * HH + fo));
                acc4(a1, *(const uint2*)(g_xr16b + (size_t)p1 * HH + fo));
                acc4(a2, *(const uint2*)(g_xr16b + (size_t)p2 * HH + fo));
                acc4(a3, *(const uint2*)(g_xr16b + (size_t)p3 * HH + fo));
            }
            for (; j < e; j++)
                acc4(a0, *(const uint2*)(g_xr16b + (size_t)__ldg(g_perm + j) * HH + fo));
            float4 zr = *(const float4*)(g_z2 + (size_t)node * HH + fo);
            zr.x = fmaxf(zr.x + (a0.x + a1.x) + (a2.x + a3.x), 0.f);
            zr.y = fmaxf(zr.y + (a0.y + a1.y) + (a2.y + a3.y), 0.f);
            zr.z = fmaxf(zr.z + (a0.z + a1.z) + (a2.z + a3.z), 0.f);
            zr.w = fmaxf(zr.w + (a0.w + a1.w) + (a2.w + a3.w), 0.f);
            uint2 xr = *(const uint2*)(g_x1h + (size_t)node * HH + fo);
            float2 xf0 = __half22float2(*reinterpret_cast<const __half2*>(&xr.x));
            float2 xf1 = __half22float2(*reinterpret_cast<const __half2*>(&xr.y));
            float4 x1 = make_float4(xf0.x, xf0.y, xf1.x, xf1.y);

            // write both halves as bf16 hi/lo into swizzled H tiles
            #pragma unroll
            for (int half = 0; half < 2; half++) {
                float4 v = half ? zr : x1;
                int kcol = half * 128 + lane * 4;
                __nv_bfloat16 h0 = __float2bfloat16(v.x), h1 = __float2bfloat16(v.y);
                __nv_bfloat16 h2 = __float2bfloat16(v.z), h3 = __float2bfloat16(v.w);
                __nv_bfloat16 l0 = __float2bfloat16(v.x - __bfloat162float(h0));
                __nv_bfloat16 l1 = __float2bfloat16(v.y - __bfloat162float(h1));
                __nv_bfloat16 l2 = __float2bfloat16(v.z - __bfloat162float(h2));
                __nv_bfloat16 l3 = __float2bfloat16(v.w - __bfloat162float(h3));
                uint32_t off = (uint32_t)(lrow * 512 + ((kcol * 2) ^ ((lrow & 7) << 4)));
                __nv_bfloat162* ph = (__nv_bfloat162*)(smem + F_AH + off);
                __nv_bfloat162* pl = (__nv_bfloat162*)(smem + F_AL + off);
                ph[0] = __halves2bfloat162(h0, h1); ph[1] = __halves2bfloat162(h2, h3);
                pl[0] = __halves2bfloat162(l0, l1); pl[1] = __halves2bfloat162(l2, l3);
            }
        }
    }
    asm volatile("cp.async.wait_group 0;" ::: "memory");
    __syncthreads();

    // ---- Stage B: HMMA m16n32k256 per warp (mt = wid&7, n-half = wid>>3) ----
    const int mt = wid & 7, nhalf = wid >> 3;
    const int qr = lane & 7, qs = lane >> 3;
    const int arow = mt * 16 + (qs & 1) * 8 + qr;
    const uint32_t aph = (uint32_t)((arow & 7) << 4);
    const uint32_t akc = (uint32_t)((qs >> 1) * 16);
    const uint32_t aH = sb + F_AH + arow * 512;
    const uint32_t aL = sb + F_AL + arow * 512;
    const int brow = nhalf * 32 + (qs >> 1) * 8 + qr;
    const uint32_t bph = (uint32_t)((brow & 7) << 4);
    const uint32_t bkc = (uint32_t)((qs & 1) * 16);
    const uint32_t wHb = sb + F_WH + brow * 512;
    const uint32_t wLb = sb + F_WL + brow * 512;

    float acc[4][4];
    #pragma unroll
    for (int nt = 0; nt < 4; nt++)
        #pragma unroll
        for (int q = 0; q < 4; q++) acc[nt][q] = 0.f;

    #pragma unroll
    for (int ks = 0; ks < 16; ks++) {
        const uint32_t ao = (akc + ks * 32) ^ aph;
        const uint32_t bo = (bkc + ks * 32) ^ bph;
        uint32_t ah[4], al[4], bh[2][4], bl[2][4];
        LDSM4(ah, aH + ao); LDSM4(al, aL + ao);
        LDSM4(bh[0], wHb + bo); LDSM4(bh[1], wHb + 8192 + bo);
        LDSM4(bl[0], wLb + bo); LDSM4(bl[1], wLb + 8192 + bo);
        #pragma unroll
        for (int nt = 0; nt < 4; nt++) {
            uint32_t* Bh = &bh[nt >> 1][2 * (nt & 1)];
            uint32_t* Bl = &bl[nt >> 1][2 * (nt & 1)];
            HMMA(acc[nt], ah, Bh);
            HMMA(acc[nt], ah, Bl);
            HMMA(acc[nt], al, Bh);
        }
    }
    __syncthreads();    // all H reads done; reuse F_AH region for logits

    // logits -> smem [128][66] floats
    float* sl = (float*)smem;
    {
        int r0 = mt * 16 + (lane >> 2);
        #pragma unroll
        for (int nt = 0; nt < 4; nt++) {
            int col = nhalf * 32 + nt * 8 + 2 * (lane & 3);
            sl[r0 * 66 + col]            = acc[nt][0];
            sl[r0 * 66 + col + 1]        = acc[nt][1];
            sl[(r0 + 8) * 66 + col]      = acc[nt][2];
            sl[(r0 + 8) * 66 + col + 1]  = acc[nt][3];
        }
    }
    __syncthreads();

    // log_softmax: 4 threads/node, 10 classes each
    const float* bsm = (const float*)(smem + F_BIAS);
    const int node = tid >> 2, q = tid & 3, c0 = q * 10;
    float a[10];
    #pragma unroll
    for (int j = 0; j < 10; j++) a[j] = sl[node * 66 + c0 + j] + bsm[c0 + j];

    float m = a[0];
    #pragma unroll
    for (int j = 1; j < 10; j++) m = fmaxf(m, a[j]);
    m = fmaxf(m, __shfl_xor_sync(0xffffffffu, m, 1));
    m = fmaxf(m, __shfl_xor_sync(0xffffffffu, m, 2));
    float s = 0.f;
    #pragma unroll
    for (int j = 0; j < 10; j++) s += __expf(a[j] - m);
    s += __shfl_xor_sync(0xffffffffu, s, 1);
    s += __shfl_xor_sync(0xffffffffu, s, 2);
    float lse = m + __logf(s);

    int gm = n0 + node;
    if (gm < NN) {
        #pragma unroll
        for (int j = 0; j < 10; j++)
            out[(size_t)gm * CC + c0 + j] = a[j] - lse;
    }
}

extern "C" void kernel_launch(void* const* d_in, const int* in_sizes, int n_in,
                              void* d_out, int out_size)
{
    const float* x       = (const float*)d_in[0];
    const int*   ei      = (const int*)  d_in[1];
    const float* W_rel1  = (const float*)d_in[2];
    const float* b_rel1  = (const float*)d_in[3];
    const float* W_root1 = (const float*)d_in[4];
    const float* W_rel2  = (const float*)d_in[5];
    const float* b_rel2  = (const float*)d_in[6];
    const float* W_root2 = (const float*)d_in[7];
    const float* W_lin   = (const float*)d_in[8];
    const float* b_lin   = (const float*)d_in[9];
    float* out = (float*)d_out;

    cudaFuncSetAttribute(layer_mma<1>, cudaFuncAttributeMaxDynamicSharedMemorySize, LSMEM);
    cudaFuncSetAttribute(layer_mma<2>, cudaFuncAttributeMaxDynamicSharedMemorySize, LSMEM);
    cudaFuncSetAttribute(final_fused, cudaFuncAttributeMaxDynamicSharedMemorySize, FSMEM);

    const int NBLK = (NN + 127) / 128;            // 782

    // Fork: CSR build on side stream, GEMM prep/layer1 on main stream.
    cudaStream_t s2;
    cudaEvent_t ev0, ev1;
    cudaStreamCreateWithFlags(&s2, cudaStreamNonBlocking);
    cudaEventCreateWithFlags(&ev0, cudaEventDisableTiming);
    cudaEventCreateWithFlags(&ev1, cudaEventDisableTiming);

    cudaEventRecord(ev0, 0);
    cudaStreamWaitEvent(s2, ev0, 0);

    // side stream: CSR build
    k_zero<<<(NN + 255) / 256, 256, 0, s2>>>();
    k_count<<<(EE + 255) / 256, 256, 0, s2>>>(ei);
    k_scan<<<98, 256, 0, s2>>>();
    k_scan2<<<1, 128, 0, s2>>>();
    k_apply<<<(NN + 255) / 256, 256, 0, s2>>>();
    k_place<<<(EE + 255) / 256, 256, 0, s2>>>(ei);
    cudaEventRecord(ev1, s2);

    // main stream: weight prep + layer1
    prep_w<<<dim3(64, 4), 256>>>(W_rel1, W_root1, W_rel2, W_root2);
    prep_wlin<<<64, 256>>>(W_lin);
    layer_mma<1><<<NBLK, 512, LSMEM>>>(x, b_rel1);

    // join: layer2's fused gather needs CSR + layer1
    cudaStreamWaitEvent(0, ev1, 0);
    layer_mma<2><<<NBLK, 512, LSMEM>>>(nullptr, b_rel2);
    final_fused<<<NBLK, 512, FSMEM>>>(b_lin, out);

    cudaEventDestroy(ev0);
    cudaEventDestroy(ev1);
    cudaStreamDestroy(s2);
}

// round 16
// speedup vs baseline: 1.1326x; 1.1326x over previous
#include <cuda_runtime.h>
#include <cuda_bf16.h>
#include <cuda_fp16.h>
#include <math.h>
#include <stdint.h>

#define NN 100000
#define EE 1600000
#define HH 128
#define CC 40

// Scratch (device globals — allocation-free per harness rules)
__device__ __half g_xr16a[(size_t)NN * HH]; // layer1 rel features (fp16 gather source)
__device__ __half g_xr16b[(size_t)NN * HH]; // layer2 rel features (fp16 gather source)
__device__ float  g_z1[(size_t)NN * HH];    // layer1: x@W_root1 + b1 (+ gathered agg)
__device__ float  g_z2[(size_t)NN * HH];    // layer2 root part
__device__ __half g_x1h[(size_t)NN * HH];   // relu(z1) fp16, for final concat
// Pre-split weights [n][k] K-major: [rel1_h, rel1_l, root1_h, root1_l,
//                                    rel2_h, rel2_l, root2_h, root2_l]
__device__ __align__(16) __nv_bfloat16 g_wsp[8 * 16384];
// W_lin pre-split, padded to [64][256] bf16 K-major: [hi, lo]
__device__ __align__(16) __nv_bfloat16 g_wlin[2 * 16384];
// CSR scratch
__device__ int g_rowptr[NN + 1];
__device__ int g_cursor[NN];
__device__ int g_perm[EE];
__device__ int g_bsum[128];

// ---------------------------------------------------------------------------
// helpers
// ---------------------------------------------------------------------------
__device__ __forceinline__ uint32_t smem_u32(const void* p) {
    uint32_t a;
    asm("{ .reg .u64 t; cvta.to.shared.u64 t, %1; cvt.u32.u64 %0, t; }"
        : "=r"(a) : "l"(p));
    return a;
}

#define LDSM4(r, addr) \
    asm volatile("ldmatrix.sync.aligned.m8n8.x4.shared.b16 {%0,%1,%2,%3}, [%4];" \
        : "=r"((r)[0]), "=r"((r)[1]), "=r"((r)[2]), "=r"((r)[3]) : "r"(addr))

#define HMMA(c, a, b) \
    asm volatile("mma.sync.aligned.m16n8k16.row.col.f32.bf16.bf16.f32 " \
        "{%0,%1,%2,%3}, {%4,%5,%6,%7}, {%8,%9}, {%0,%1,%2,%3};" \
        : "+f"((c)[0]), "+f"((c)[1]), "+f"((c)[2]), "+f"((c)[3]) \
        : "r"((a)[0]), "r"((a)[1]), "r"((a)[2]), "r"((a)[3]), \
          "r"((b)[0]), "r"((b)[1]))

#define CP_ASYNC16(dst, src) \
    asm volatile("cp.async.cg.shared.global [%0], [%1], 16;" \
                 :: "r"(dst), "l"(src) : "memory")

__device__ __forceinline__ void acc4(float4& a, uint2 r) {
    float2 f0 = __half22float2(*reinterpret_cast<const __half2*>(&r.x));
    float2 f1 = __half22float2(*reinterpret_cast<const __half2*>(&r.y));
    a.x += f0.x; a.y += f0.y; a.z += f1.x; a.w += f1.y;
}

// ---------------------------------------------------------------------------
// Weight prep: split each 128x128 W ([k][n]) into bf16 hi/lo, transposed to
// [n][k] K-major linear. Tiny one-shot kernel.
// ---------------------------------------------------------------------------
__global__ void prep_w(const float* __restrict__ Wr1, const float* __restrict__ Wt1,
                       const float* __restrict__ Wr2, const float* __restrict__ Wt2)
{
    int idx = blockIdx.x * 256 + threadIdx.x;   // 0..16383
    const float* src = (blockIdx.y == 0) ? Wr1 : (blockIdx.y == 1) ? Wt1
                     : (blockIdx.y == 2) ? Wr2 : Wt2;
    float w = src[idx];                          // W[k][n]
    int k = idx >> 7, n = idx & 127;
    __nv_bfloat16 h = __float2bfloat16(w);
    __nv_bfloat16 l = __float2bfloat16(w - __bfloat162float(h));
    int tb = blockIdx.y * 2;
    g_wsp[(size_t)tb * 16384 + n * 128 + k] = h;
    g_wsp[(size_t)(tb + 1) * 16384 + n * 128 + k] = l;
}

// W_lin [256][40] -> padded [64][256] bf16 hi/lo, [c][k] K-major
__global__ void prep_wlin(const float* __restrict__ Wlin)
{
    int idx = blockIdx.x * 256 + threadIdx.x;   // 0..16383
    int c = idx >> 8, k = idx & 255;
    float w = (c < CC) ? Wlin[k * CC + c] : 0.f;
    __nv_bfloat16 h = __float2bfloat16(w);
    __nv_bfloat16 l = __float2bfloat16(w - __bfloat162float(h));
    g_wlin[idx] = h;
    g_wlin[16384 + idx] = l;
}

// ---------------------------------------------------------------------------
// CSR build kernels
// ---------------------------------------------------------------------------
__global__ void k_zero() {
    int i = blockIdx.x * 256 + threadIdx.x;
    if (i < NN) g_cursor[i] = 0;
}
__global__ void k_count(const int* __restrict__ ei) {
    int e = blockIdx.x * 256 + threadIdx.x;
    if (e < EE) atomicAdd(&g_cursor[__ldg(ei + EE + e)], 1);
}
__global__ void k_scan(void) {
    __shared__ int wsum[8];
    __shared__ int wexc[8];
    int t = threadIdx.x, b = blockIdx.x;
    int base = b * 1024 + t * 4;
    int x0 = (base + 0 < NN) ? g_cursor[base + 0] : 0;
    int x1 = (base + 1 < NN) ? g_cursor[base + 1] : 0;
    int x2 = (base + 2 < NN) ? g_cursor[base + 2] : 0;
    int x3 = (base + 3 < NN) ? g_cursor[base + 3] : 0;
    int s1 = x0, s2 = x0 + x1, s3 = x0 + x1 + x2, T = s3 + x3;
    int lane = t & 31, w = t >> 5;
    int inc = T;
    #pragma unroll
    for (int d = 1; d < 32; d <<= 1) {
        int v = __shfl_up_sync(0xffffffffu, inc, d);
        if (lane >= d) inc += v;
    }
    int wex = inc - T;
    if (lane == 31) wsum[w] = inc;
    __syncthreads();
    if (t == 0) {
        int r = 0;
        #pragma unroll
        for (int i = 0; i < 8; i++) { int v = wsum[i]; wexc[i] = r; r += v; }
        g_bsum[b] = r;
    }
    __syncthreads();
    int ex = wexc[w] + wex;
    if (base + 0 < NN) g_rowptr[base + 0] = ex;
    if (base + 1 < NN) g_rowptr[base + 1] = ex + s1;
    if (base + 2 < NN) g_rowptr[base + 2] = ex + s2;
    if (base + 3 < NN) g_rowptr[base + 3] = ex + s3;
}
__global__ void k_scan2(void) {       // exclusive scan of 98 block sums
    __shared__ int s[128];
    int t = threadIdx.x;
    s[t] = (t < 98) ? g_bsum[t] : 0;
    __syncthreads();
    if (t == 0) {
        int r = 0;
        for (int i = 0; i < 98; i++) { int v = s[i]; s[i] = r; r += v; }
    }
    __syncthreads();
    if (t < 98) g_bsum[t] = s[t];
}
__global__ void k_apply(void) {
    int i = blockIdx.x * 256 + threadIdx.x;
    if (i < NN) {
        int v = g_rowptr[i] + g_bsum[i >> 10];
        g_rowptr[i] = v;
        g_cursor[i] = v;
    }
    if (i == 0) g_rowptr[NN] = EE;
}
__global__ void k_place(const int* __restrict__ ei) {
    int e = blockIdx.x * 256 + threadIdx.x;
    if (e < EE) {
        int d = __ldg(ei + EE + e);
        int p = atomicAdd(&g_cursor[d], 1);
        g_perm[p] = __ldg(ei + e);
    }
}

// ---------------------------------------------------------------------------
// CSR gather (layer 1): z1[n] += sum_{j in N(n)} g_xr16a[perm[j]]. No atomics.
// Dedicated high-occupancy kernel (no smem) — latency hidden by many warps.
// One warp per node; lane owns 4 fp16 features (uint2); 4-way unrolled.
// ---------------------------------------------------------------------------
__global__ __launch_bounds__(256) void gather1(void)
{
    int node = blockIdx.x * 8 + (threadIdx.x >> 5);
    int lane = threadIdx.x & 31;
    if (node >= NN) return;
    int s = g_rowptr[node], e = g_rowptr[node + 1];
    const size_t fo = (size_t)lane * 4;
    float4 a0 = make_float4(0.f, 0.f, 0.f, 0.f), a1 = a0, a2 = a0, a3 = a0;
    int j = s;
    for (; j + 3 < e; j += 4) {
        int p0 = __ldg(g_perm + j),     p1 = __ldg(g_perm + j + 1);
        int p2 = __ldg(g_perm + j + 2), p3 = __ldg(g_perm + j + 3);
        acc4(a0, *(const uint2*)(g_xr16a + (size_t)p0 * HH + fo));
        acc4(a1, *(const uint2*)(g_xr16a + (size_t)p1 * HH + fo));
        acc4(a2, *(const uint2*)(g_xr16a + (size_t)p2 * HH + fo));
        acc4(a3, *(const uint2*)(g_xr16a + (size_t)p3 * HH + fo));
    }
    for (; j < e; j++)
        acc4(a0, *(const uint2*)(g_xr16a + (size_t)__ldg(g_perm + j) * HH + fo));
    float4* zp = (float4*)(g_z1 + (size_t)node * HH + fo);
    float4 z = *zp;
    z.x += (a0.x + a1.x) + (a2.x + a3.x);
    z.y += (a0.y + a1.y) + (a2.y + a3.y);
    z.z += (a0.z + a1.z) + (a2.z + a3.z);
    z.w += (a0.w + a1.w) + (a2.w + a3.w);
    *zp = z;
}

// ---------------------------------------------------------------------------
// Layer GEMM: one CTA = 128 rows, computes BOTH A@W_rel -> xr16 out (fp16) and
// A@W_root + b -> z (two sequential N-phases). bf16 hi/lo split, fp32 accum.
// LAYER==1: A = x (fp32 global); rel out -> g_xr16a.
// LAYER==2: A = relu(g_z1) (z1 already has agg added by gather1); also writes
//           x1 = relu(z1) to g_x1h (fp16); rel out -> g_xr16b.
// 512 threads (16 warps: 4M x 4N). Weights staged via cp.async.
// ---------------------------------------------------------------------------
#define OFF_AH 0
#define OFF_AL 32768
#define OFF_W  65536          // 4 tiles: rel_h, rel_l, root_h, root_l (32KB each)
#define LSMEM  196608

template <int LAYER>
__global__ __launch_bounds__(512, 1) void layer_mma(
    const float* __restrict__ Ain, const float* __restrict__ bias)
{
    extern __shared__ char smem[];
    const uint32_t sb = smem_u32(smem);
    const int tid = threadIdx.x, wid = tid >> 5, lane = tid & 31;
    const int m0 = blockIdx.x * 128;

    const float* A = (LAYER == 1) ? Ain : g_z1;
    float* outz = (LAYER == 1) ? g_z1 : g_z2;
    __half* outxr = (LAYER == 1) ? g_xr16a : g_xr16b;
    const __nv_bfloat16* wsrc = g_wsp + (size_t)(LAYER - 1) * 4 * 16384;

    // ---- weights: 4 tiles (128KB) via cp.async into swizzled smem ----
    {
        const float4* ws = (const float4*)wsrc;   // 8192 float4
        #pragma unroll
        for (int i = 0; i < 16; i++) {
            int s = tid + i * 512;                // 0..8191
            int t4 = s >> 11;
            int r = s & 2047;
            int n = r >> 4, c = r & 15;
            uint32_t dst = sb + OFF_W + t4 * 32768
                         + (uint32_t)(n * 256 + ((c * 16) ^ ((n & 7) << 4)));
            CP_ASYNC16(dst, ws + s);
        }
        asm volatile("cp.async.commit_group;" ::: "memory");
    }

    // ---- A tile: fp32 load, relu (+ save x1h) for layer2, hi/lo split ----
    #pragma unroll
    for (int i = 0; i < 8; i++) {
        int f = tid + i * 512;                    // 0..4095 float4 slots
        int row = f >> 5;
        int k4 = (f & 31) << 2;
        int gm = m0 + row;
        float4 v = make_float4(0.f, 0.f, 0.f, 0.f);
        if (gm < NN) v = *(const float4*)(A + (size_t)gm * HH + k4);
        if (LAYER == 2) {
            v.x = fmaxf(v.x, 0.f); v.y = fmaxf(v.y, 0.f);
            v.z = fmaxf(v.z, 0.f); v.w = fmaxf(v.w, 0.f);
            if (gm < NN) {
                __half2 p0 = __floats2half2_rn(v.x, v.y);
                __half2 p1 = __floats2half2_rn(v.z, v.w);
                uint2 o = make_uint2(*(uint32_t*)&p0, *(uint32_t*)&p1);
                *(uint2*)(g_x1h + (size_t)gm * HH + k4) = o;
            }
        }
        __nv_bfloat16 h0 = __float2bfloat16(v.x), h1 = __float2bfloat16(v.y);
        __nv_bfloat16 h2 = __float2bfloat16(v.z), h3 = __float2bfloat16(v.w);
        __nv_bfloat16 l0 = __float2bfloat16(v.x - __bfloat162float(h0));
        __nv_bfloat16 l1 = __float2bfloat16(v.y - __bfloat162float(h1));
        __nv_bfloat16 l2 = __float2bfloat16(v.z - __bfloat162float(h2));
        __nv_bfloat16 l3 = __float2bfloat16(v.w - __bfloat162float(h3));
        uint32_t off = (uint32_t)(row * 256 + ((k4 * 2) ^ ((row & 7) << 4)));
        __nv_bfloat162* ph = (__nv_bfloat162*)(smem + OFF_AH + off);
        __nv_bfloat162* pl = (__nv_bfloat162*)(smem + OFF_AL + off);
        ph[0] = __halves2bfloat162(h0, h1); ph[1] = __halves2bfloat162(h2, h3);
        pl[0] = __halves2bfloat162(l0, l1); pl[1] = __halves2bfloat162(l2, l3);
    }
    asm volatile("cp.async.wait_group 0;" ::: "memory");
    __syncthreads();

    // ---- warp tiling: 4(M) x 4(N); warp tile M32 x N32 ----
    const int mbase = (wid >> 2) * 32;
    const int nbase = (wid & 3) * 32;
    const int qr = lane & 7, qs = lane >> 3;

    const int arow = mbase + (qs & 1) * 8 + qr;
    const uint32_t aph = (uint32_t)((arow & 7) << 4);
    const uint32_t akc = (uint32_t)((qs >> 1) * 16);
    const uint32_t aH = sb + OFF_AH + arow * 256;
    const uint32_t aL = sb + OFF_AL + arow * 256;
    const int brow = nbase + (qs >> 1) * 8 + qr;
    const uint32_t bph = (uint32_t)((brow & 7) << 4);
    const uint32_t bkc = (uint32_t)((qs & 1) * 16);
    const uint32_t brofs = (uint32_t)(brow * 256);

    #pragma unroll
    for (int which = 0; which < 2; which++) {
        const uint32_t wHb = sb + OFF_W + which * 65536 + brofs;
        const uint32_t wLb = wHb + 32768;

        float acc[2][4][4];
        #pragma unroll
        for (int mt = 0; mt < 2; mt++)
            #pragma unroll
            for (int nt = 0; nt < 4; nt++)
                #pragma unroll
                for (int q = 0; q < 4; q++) acc[mt][nt][q] = 0.f;

        #pragma unroll
        for (int ks = 0; ks < 8; ks++) {
            const uint32_t ao = (akc + ks * 32) ^ aph;
            const uint32_t bo = (bkc + ks * 32) ^ bph;
            uint32_t ah[2][4], al[2][4], bh[2][4], bl[2][4];
            LDSM4(ah[0], aH + ao); LDSM4(ah[1], aH + 4096 + ao);
            LDSM4(al[0], aL + ao); LDSM4(al[1], aL + 4096 + ao);
            LDSM4(bh[0], wHb + bo); LDSM4(bh[1], wHb + 4096 + bo);
            LDSM4(bl[0], wLb + bo); LDSM4(bl[1], wLb + 4096 + bo);
            #pragma unroll
            for (int mt = 0; mt < 2; mt++)
                #pragma unroll
                for (int nt = 0; nt < 4; nt++) {
                    uint32_t* Bh = &bh[nt >> 1][2 * (nt & 1)];
                    uint32_t* Bl = &bl[nt >> 1][2 * (nt & 1)];
                    HMMA(acc[mt][nt], ah[mt], Bh);
                    HMMA(acc[mt][nt], ah[mt], Bl);
                    HMMA(acc[mt][nt], al[mt], Bh);
                }
        }

        #pragma unroll
        for (int mt = 0; mt < 2; mt++) {
            int mrow = m0 + mbase + mt * 16 + (lane >> 2);
            #pragma unroll
            for (int nt = 0; nt < 4; nt++) {
                int col = nbase + nt * 8 + 2 * (lane & 3);
                if (which) {
                    float bx = __ldg(bias + col), by = __ldg(bias + col + 1);
                    if (mrow < NN)
                        *(float2*)(outz + (size_t)mrow * HH + col) =
                            make_float2(acc[mt][nt][0] + bx, acc[mt][nt][1] + by);
                    if (mrow + 8 < NN)
                        *(float2*)(outz + (size_t)(mrow + 8) * HH + col) =
                            make_float2(acc[mt][nt][2] + bx, acc[mt][nt][3] + by);
                } else {
                    if (mrow < NN) {
                        __half2 hv = __floats2half2_rn(acc[mt][nt][0], acc[mt][nt][1]);
                        *(uint32_t*)(outxr + (size_t)mrow * HH + col) = *(uint32_t*)&hv;
                    }
                    if (mrow + 8 < NN) {
                        __half2 hv = __floats2half2_rn(acc[mt][nt][2], acc[mt][nt][3]);
                        *(uint32_t*)(outxr + (size_t)(mrow + 8) * HH + col) = *(uint32_t*)&hv;
                    }
                }
            }
        }
    }
}

// ---------------------------------------------------------------------------
// Fused gather2 + final (HMMA): per 128-node CTA,
//   stage A: warp-per-node gather agg from g_xr16b (fp16), + g_z2 root, relu;
//            x1 from g_x1h (fp16, already relu'd); H = [x1|z2] bf16 hi/lo.
//   stage B: logits = H @ W_lin^T via m16n8k16 (3-product split), bias +
//            log_softmax from smem logits. 512 threads.
// ---------------------------------------------------------------------------
#define F_AH 0                 // 128 x 512B (bf16 hi)
#define F_AL 65536             // 128 x 512B (bf16 lo)
#define F_WH 131072            // 64 x 512B
#define F_WL 163840            // 64 x 512B
#define F_BIAS 196608          // 40 floats
#define FSMEM  196864

__global__ __launch_bounds__(512, 1) void final_fused(
    const float* __restrict__ blin, float* __restrict__ out)
{
    extern __shared__ char smem[];
    const uint32_t sb = smem_u32(smem);
    const int tid = threadIdx.x, wid = tid >> 5, lane = tid & 31;
    const int n0 = blockIdx.x * 128;

    // ---- W_lin hi/lo tiles (64KB) via cp.async ----
    {
        const float4* ws = (const float4*)g_wlin;  // 4096 uint4
        #pragma unroll
        for (int i = 0; i < 8; i++) {
            int s = tid + i * 512;                 // 0..4095
            int t4 = s >> 11;                      // 0 hi, 1 lo
            int r = s & 2047;
            int n = r >> 5, c = r & 31;
            uint32_t dst = sb + F_WH + t4 * 32768
                         + (uint32_t)(n * 512 + ((c * 16) ^ ((n & 7) << 4)));
            CP_ASYNC16(dst, ws + s);
        }
        asm volatile("cp.async.commit_group;" ::: "memory");
    }
    if (tid < CC) ((float*)(smem + F_BIAS))[tid] = blin[tid];

    // ---- Stage A: gather + convert; each warp handles 8 nodes ----
    const size_t fo = (size_t)lane * 4;
    #pragma unroll 1
    for (int i = 0; i < 8; i++) {
        int node = n0 + wid * 8 + i;
        int lrow = wid * 8 + i;
        if (node < NN) {
            int s = g_rowptr[node], e = g_rowptr[node + 1];
            float4 a0 = make_float4(0.f, 0.f, 0.f, 0.f), a1 = a0, a2 = a0, a3 = a0;
            int j = s;
            for (; j + 3 < e; j += 4) {
                int p0 = __ldg(g_perm + j),     p1 = __ldg(g_perm + j + 1);
                int p2 = __ldg(g_perm + j + 2), p3 = __ldg(g_perm + j + 3);
                acc4(a0, *(const uint2*)(g_xr16b + (size_t)p0 * HH + fo));
                acc4(a1, *(const uint2*)(g_xr16b + (size_t)p1 * HH + fo));
                acc4(a2, *(const uint2*)(g_xr16b + (size_t)p2 * HH + fo));
                acc4(a3, *(const uint2*)(g_xr16b + (size_t)p3 * HH + fo));
            }
            for (; j < e; j++)
                acc4(a0, *(const uint2*)(g_xr16b + (size_t)__ldg(g_perm + j) * HH + fo));
            float4 zr = *(const float4*)(g_z2 + (size_t)node * HH + fo);
            zr.x = fmaxf(zr.x + (a0.x + a1.x) + (a2.x + a3.x), 0.f);
            zr.y = fmaxf(zr.y + (a0.y + a1.y) + (a2.y + a3.y), 0.f);
            zr.z = fmaxf(zr.z + (a0.z + a1.z) + (a2.z + a3.z), 0.f);
            zr.w = fmaxf(zr.w + (a0.w + a1.w) + (a2.w + a3.w), 0.f);
            uint2 xr = *(const uint2*)(g_x1h + (size_t)node * HH + fo);
            float2 xf0 = __half22float2(*reinterpret_cast<const __half2*>(&xr.x));
            float2 xf1 = __half22float2(*reinterpret_cast<const __half2*>(&xr.y));
            float4 x1 = make_float4(xf0.x, xf0.y, xf1.x, xf1.y);

            // write both halves as bf16 hi/lo into swizzled H tiles
            #pragma unroll
            for (int half = 0; half < 2; half++) {
                float4 v = half ? zr : x1;
                int kcol = half * 128 + lane * 4;
                __nv_bfloat16 h0 = __float2bfloat16(v.x), h1 = __float2bfloat16(v.y);
                __nv_bfloat16 h2 = __float2bfloat16(v.z), h3 = __float2bfloat16(v.w);
                __nv_bfloat16 l0 = __float2bfloat16(v.x - __bfloat162float(h0));
                __nv_bfloat16 l1 = __float2bfloat16(v.y - __bfloat162float(h1));
                __nv_bfloat16 l2 = __float2bfloat16(v.z - __bfloat162float(h2));
                __nv_bfloat16 l3 = __float2bfloat16(v.w - __bfloat162float(h3));
                uint32_t off = (uint32_t)(lrow * 512 + ((kcol * 2) ^ ((lrow & 7) << 4)));
                __nv_bfloat162* ph = (__nv_bfloat162*)(smem + F_AH + off);
                __nv_bfloat162* pl = (__nv_bfloat162*)(smem + F_AL + off);
                ph[0] = __halves2bfloat162(h0, h1); ph[1] = __halves2bfloat162(h2, h3);
                pl[0] = __halves2bfloat162(l0, l1); pl[1] = __halves2bfloat162(l2, l3);
            }
        }
    }
    asm volatile("cp.async.wait_group 0;" ::: "memory");
    __syncthreads();

    // ---- Stage B: HMMA m16n32k256 per warp (mt = wid&7, n-half = wid>>3) ----
    const int mt = wid & 7, nhalf = wid >> 3;
    const int qr = lane & 7, qs = lane >> 3;
    const int arow = mt * 16 + (qs & 1) * 8 + qr;
    const uint32_t aph = (uint32_t)((arow & 7) << 4);
    const uint32_t akc = (uint32_t)((qs >> 1) * 16);
    const uint32_t aH = sb + F_AH + arow * 512;
    const uint32_t aL = sb + F_AL + arow * 512;
    const int brow = nhalf * 32 + (qs >> 1) * 8 + qr;
    const uint32_t bph = (uint32_t)((brow & 7) << 4);
    const uint32_t bkc = (uint32_t)((qs & 1) * 16);
    const uint32_t wHb = sb + F_WH + brow * 512;
    const uint32_t wLb = sb + F_WL + brow * 512;

    float acc[4][4];
    #pragma unroll
    for (int nt = 0; nt < 4; nt++)
        #pragma unroll
        for (int q = 0; q < 4; q++) acc[nt][q] = 0.f;

    #pragma unroll
    for (int ks = 0; ks < 16; ks++) {
        const uint32_t ao = (akc + ks * 32) ^ aph;
        const uint32_t bo = (bkc + ks * 32) ^ bph;
        uint32_t ah[4], al[4], bh[2][4], bl[2][4];
        LDSM4(ah, aH + ao); LDSM4(al, aL + ao);
        LDSM4(bh[0], wHb + bo); LDSM4(bh[1], wHb + 8192 + bo);
        LDSM4(bl[0], wLb + bo); LDSM4(bl[1], wLb + 8192 + bo);
        #pragma unroll
        for (int nt = 0; nt < 4; nt++) {
            uint32_t* Bh = &bh[nt >> 1][2 * (nt & 1)];
            uint32_t* Bl = &bl[nt >> 1][2 * (nt & 1)];
            HMMA(acc[nt], ah, Bh);
            HMMA(acc[nt], ah, Bl);
            HMMA(acc[nt], al, Bh);
        }
    }
    __syncthreads();    // all H reads done; reuse F_AH region for logits

    // logits -> smem [128][66] floats
    float* sl = (float*)smem;
    {
        int r0 = mt * 16 + (lane >> 2);
        #pragma unroll
        for (int nt = 0; nt < 4; nt++) {
            int col = nhalf * 32 + nt * 8 + 2 * (lane & 3);
            sl[r0 * 66 + col]            = acc[nt][0];
            sl[r0 * 66 + col + 1]        = acc[nt][1];
            sl[(r0 + 8) * 66 + col]      = acc[nt][2];
            sl[(r0 + 8) * 66 + col + 1]  = acc[nt][3];
        }
    }
    __syncthreads();

    // log_softmax: 4 threads/node, 10 classes each
    const float* bsm = (const float*)(smem + F_BIAS);
    const int node = tid >> 2, q = tid & 3, c0 = q * 10;
    float a[10];
    #pragma unroll
    for (int j = 0; j < 10; j++) a[j] = sl[node * 66 + c0 + j] + bsm[c0 + j];

    float m = a[0];
    #pragma unroll
    for (int j = 1; j < 10; j++) m = fmaxf(m, a[j]);
    m = fmaxf(m, __shfl_xor_sync(0xffffffffu, m, 1));
    m = fmaxf(m, __shfl_xor_sync(0xffffffffu, m, 2));
    float s = 0.f;
    #pragma unroll
    for (int j = 0; j < 10; j++) s += __expf(a[j] - m);
    s += __shfl_xor_sync(0xffffffffu, s, 1);
    s += __shfl_xor_sync(0xffffffffu, s, 2);
    float lse = m + __logf(s);

    int gm = n0 + node;
    if (gm < NN) {
        #pragma unroll
        for (int j = 0; j < 10; j++)
            out[(size_t)gm * CC + c0 + j] = a[j] - lse;
    }
}

extern "C" void kernel_launch(void* const* d_in, const int* in_sizes, int n_in,
                              void* d_out, int out_size)
{
    const float* x       = (const float*)d_in[0];
    const int*   ei      = (const int*)  d_in[1];
    const float* W_rel1  = (const float*)d_in[2];
    const float* b_rel1  = (const float*)d_in[3];
    const float* W_root1 = (const float*)d_in[4];
    const float* W_rel2  = (const float*)d_in[5];
    const float* b_rel2  = (const float*)d_in[6];
    const float* W_root2 = (const float*)d_in[7];
    const float* W_lin   = (const float*)d_in[8];
    const float* b_lin   = (const float*)d_in[9];
    float* out = (float*)d_out;

    cudaFuncSetAttribute(layer_mma<1>, cudaFuncAttributeMaxDynamicSharedMemorySize, LSMEM);
    cudaFuncSetAttribute(layer_mma<2>, cudaFuncAttributeMaxDynamicSharedMemorySize, LSMEM);
    cudaFuncSetAttribute(final_fused, cudaFuncAttributeMaxDynamicSharedMemorySize, FSMEM);

    const int NBLK = (NN + 127) / 128;            // 782

    // Fork: CSR build on side stream, GEMM prep/layer1 on main stream.
    cudaStream_t s2;
    cudaEvent_t ev0, ev1;
    cudaStreamCreateWithFlags(&s2, cudaStreamNonBlocking);
    cudaEventCreateWithFlags(&ev0, cudaEventDisableTiming);
    cudaEventCreateWithFlags(&ev1, cudaEventDisableTiming);

    cudaEventRecord(ev0, 0);
    cudaStreamWaitEvent(s2, ev0, 0);

    // side stream: CSR build
    k_zero<<<(NN + 255) / 256, 256, 0, s2>>>();
    k_count<<<(EE + 255) / 256, 256, 0, s2>>>(ei);
    k_scan<<<98, 256, 0, s2>>>();
    k_scan2<<<1, 128, 0, s2>>>();
    k_apply<<<(NN + 255) / 256, 256, 0, s2>>>();
    k_place<<<(EE + 255) / 256, 256, 0, s2>>>(ei);
    cudaEventRecord(ev1, s2);

    // main stream: weight prep + layer1
    prep_w<<<dim3(64, 4), 256>>>(W_rel1, W_root1, W_rel2, W_root2);
    prep_wlin<<<64, 256>>>(W_lin);
    layer_mma<1><<<NBLK, 512, LSMEM>>>(x, b_rel1);

    // join: gather1 needs CSR + layer1
    cudaStreamWaitEvent(0, ev1, 0);
    gather1<<<(NN + 7) / 8, 256>>>();
    layer_mma<2><<<NBLK, 512, LSMEM>>>(nullptr, b_rel2);
    final_fused<<<NBLK, 512, FSMEM>>>(b_lin, out);

    cudaEventDestroy(ev0);
    cudaEventDestroy(ev1);
    cudaStreamDestroy(s2);
}